// round 15
// baseline (speedup 1.0000x reference)
#include <cuda_runtime.h>
#include <cuda_fp16.h>
#include <cstdint>

// ===========================================================================
// Problem constants
// ===========================================================================
#define D        144
#define NROWS    4096
#define NCODES   50257
#define ZQ_ELEMS (NROWS * D)

#define BM       128                        // rows per CTA
#define BN       128                        // codes per tensor tile
#define NSPLIT   9
#define TPS      35                         // tensor tiles per split
#define TILES_T  (NSPLIT * TPS)             // 315 tensor tiles
#define FBASE    (TILES_T * BN)             // 40320: first FFMA-screened code
#define FPW      553                        // codes per FFMA warp (18 warps)

#define CAP      4096                       // candidate slots per row
#define ESCALE   1024.0f                    // emb pre-scale for fp16 tensor path
#define CAPW_T   (3e-5f * ESCALE)           // tensor capture window (scaled)
#define CAPW_F   3e-5f                      // ffma capture window (unscaled)
#define ASTRIDE  152                        // A smem row stride (fp16 elems)

// ===========================================================================
// Global scratch (device globals only — no cudaMalloc)
// ===========================================================================
__device__ unsigned long long g_best[NROWS];
__device__ float    g_nrm[NCODES];
__device__ float    g_zn[NROWS];
__device__ float    g_part[NROWS];
__device__ int      g_cnt[NROWS];
__device__ unsigned g_cand[(size_t)NROWS * CAP];
__device__ __align__(16) __half g_embh[(size_t)NCODES * D];

__device__ __forceinline__ unsigned ordered_bits(float s) {
    unsigned b = __float_as_uint(s);
    return b ^ ((unsigned)((int)b >> 31) | 0x80000000u);
}
__device__ __forceinline__ unsigned pack_h2(float lo, float hi) {
    __half2 h = __floats2half2_rn(lo, hi);
    return *(unsigned*)&h;
}
__device__ __forceinline__ uint32_t smem_u32(const void* p) {
    uint32_t a;
    asm("{ .reg .u64 t; cvta.to.shared.u64 t, %1; cvt.u32.u64 %0, t; }"
        : "=r"(a) : "l"(p));
    return a;
}
__device__ __forceinline__ void ldsm4(unsigned a[4], unsigned addr) {
    asm volatile("ldmatrix.sync.aligned.m8n8.x4.shared.b16 {%0,%1,%2,%3}, [%4];"
                 : "=r"(a[0]), "=r"(a[1]), "=r"(a[2]), "=r"(a[3]) : "r"(addr));
}
__device__ __forceinline__ void mma16816h(unsigned c[2], const unsigned a[4],
                                          const unsigned b0, const unsigned b1) {
    asm volatile(
        "mma.sync.aligned.m16n8k16.row.col.f16.f16.f16.f16 "
        "{%0,%1}, {%2,%3,%4,%5}, {%6,%7}, {%0,%1};"
        : "+r"(c[0]), "+r"(c[1])
        : "r"(a[0]), "r"(a[1]), "r"(a[2]), "r"(a[3]), "r"(b0), "r"(b1));
}
// fp16x2 -> packed f32x2 (exact conversion)
__device__ __forceinline__ unsigned long long h2f2(unsigned u) {
    unsigned long long r;
    asm("{\n\t.reg .b16 h0, h1;\n\t.reg .f32 f0, f1;\n\t"
        "mov.b32 {h0, h1}, %1;\n\t"
        "cvt.f32.f16 f0, h0;\n\tcvt.f32.f16 f1, h1;\n\t"
        "mov.b64 %0, {f0, f1};\n\t}" : "=l"(r) : "r"(u));
    return r;
}
#define FMA2(acc, a, b) \
    asm("fma.rn.f32x2 %0, %1, %2, %0;" : "+l"(acc) : "l"(a), "l"(b))
#define UNPK(lo, hi, a) \
    asm("mov.b64 {%0, %1}, %2;" : "=f"(lo), "=f"(hi) : "l"(a))

// ===========================================================================
// Kernel 1: norms, scaled-fp16 emb copy, scratch reset
// ===========================================================================
__global__ void prep_kernel(const float* __restrict__ z,
                            const float* __restrict__ emb) {
    int t = blockIdx.x * 256 + threadIdx.x;
    if (t < NROWS) {
        g_best[t] = 0xFFFFFFFFFFFFFFFFull;
        g_cnt[t] = 0;
        const float4* p = (const float4*)(z + (size_t)t * D);
        float s = 0.f;
        #pragma unroll
        for (int i = 0; i < 36; i++) {
            float4 v = p[i];
            s += v.x * v.x + v.y * v.y + v.z * v.z + v.w * v.w;
        }
        g_zn[t] = s;
    }
    if (t < NCODES) {
        const float4* p = (const float4*)(emb + (size_t)t * D);
        uint2* dst = (uint2*)(g_embh + (size_t)t * D);
        float s = 0.f;
        #pragma unroll
        for (int i = 0; i < 36; i++) {
            float4 v = p[i];
            s += v.x * v.x + v.y * v.y + v.z * v.z + v.w * v.w;
            dst[i] = make_uint2(pack_h2(v.x * ESCALE, v.y * ESCALE),
                                pack_h2(v.z * ESCALE, v.w * ESCALE));
        }
        g_nrm[t] = s;
    }
}

// ===========================================================================
// Kernel 2: hybrid screening. Warps 0-7: fp16 HMMA on codes [0, FBASE).
// Warps 8-9: f32x2 FFMA on codes [FBASE, NCODES). Barrier-free mainloops.
// grid(32, 9), 320 threads, 2 CTAs/SM
// ===========================================================================
__device__ __forceinline__ void loadB(unsigned b[4][2], int c0, int ks,
                                      int nwarp, int lane) {
    #pragma unroll
    for (int nt = 0; nt < 4; nt++) {
        int code = c0 + nwarp * 32 + nt * 8 + (lane >> 2);
        const __half* p = g_embh + (size_t)code * D + ks * 16 + (lane & 3) * 2;
        b[nt][0] = *(const unsigned*)p;
        b[nt][1] = *(const unsigned*)(p + 8);
    }
}

__global__ void __launch_bounds__(320, 2)
screen_kernel(const float* __restrict__ z, const float* __restrict__ emb) {
    __shared__ __half As[BM * ASTRIDE];

    const int tid  = threadIdx.x;
    const int lane = tid & 31;
    const int wid  = tid >> 5;
    const int row0 = blockIdx.x * BM;

    // Load z tile -> fp16 smem (row-major, stride 152). Threads 0..255 only.
    if (tid < 256) {
        int row = tid >> 1, half = tid & 1;
        const float4* src = (const float4*)(z + (size_t)(row0 + row) * D + half * 72);
        unsigned eo = row * ASTRIDE + half * 72;
        #pragma unroll
        for (int j = 0; j < 18; j++) {
            float4 v = src[j];
            *(uint2*)(As + eo + j * 4) =
                make_uint2(pack_h2(v.x, v.y), pack_h2(v.z, v.w));
        }
    }
    __syncthreads();

    if (wid < 8) {
        // ================= TENSOR SCREEN (R12 champion, tiles 0..314) ======
        const int mwarp = wid >> 2;       // 0..1
        const int nwarp = wid & 3;        // 0..3
        const unsigned asbase = smem_u32(As);
        const int tile0 = blockIdx.y * TPS;
        const int tile1 = tile0 + TPS;    // <= 315

        float rmax[8];
        #pragma unroll
        for (int i = 0; i < 8; i++) rmax[i] = __int_as_float(0xff800000);

        for (int ti = tile0; ti < tile1; ++ti) {
            const int c0 = ti * BN;

            unsigned acc[4][4][2];
            #pragma unroll
            for (int mt = 0; mt < 4; mt++)
                #pragma unroll
                for (int nt = 0; nt < 4; nt++) {
                    acc[mt][nt][0] = 0u; acc[mt][nt][1] = 0u;
                }

            unsigned b[4][2], bn[4][2];
            loadB(b, c0, 0, nwarp, lane);

            #pragma unroll
            for (int ks = 0; ks < 9; ks++) {
                if (ks < 8) loadB(bn, c0, ks + 1, nwarp, lane);
                unsigned a[4][4];
                #pragma unroll
                for (int mt = 0; mt < 4; mt++) {
                    unsigned arow = mwarp * 64 + mt * 16 + (lane & 15);
                    unsigned abyte = (arow * ASTRIDE + ks * 16 + (lane >> 4) * 8) * 2;
                    ldsm4(a[mt], asbase + abyte);
                }
                #pragma unroll
                for (int mt = 0; mt < 4; mt++)
                    #pragma unroll
                    for (int nt = 0; nt < 4; nt++)
                        mma16816h(acc[mt][nt], a[mt], b[nt][0], b[nt][1]);
                #pragma unroll
                for (int nt = 0; nt < 4; nt++) {
                    b[nt][0] = bn[nt][0]; b[nt][1] = bn[nt][1];
                }
            }

            // Epilogue (R12/R4 order): capture then pool
            #pragma unroll
            for (int mt = 0; mt < 4; mt++) {
                float vf[4][2][2];
                #pragma unroll
                for (int nt = 0; nt < 4; nt++)
                    #pragma unroll
                    for (int h = 0; h < 2; h++) {
                        __half2 hv = *(__half2*)&acc[mt][nt][h];
                        float2 f = __half22float2(hv);
                        vf[nt][h][0] = f.x;
                        vf[nt][h][1] = f.y;
                        rmax[mt * 2 + h] = fmaxf(rmax[mt * 2 + h], fmaxf(f.x, f.y));
                    }
                #pragma unroll
                for (int nt = 0; nt < 4; nt++)
                    #pragma unroll
                    for (int h = 0; h < 2; h++)
                        #pragma unroll
                        for (int q = 0; q < 2; q++) {
                            float v = vf[nt][h][q];
                            if (v >= rmax[mt * 2 + h] - CAPW_T) {
                                int c = c0 + nwarp * 32 + nt * 8 + (lane & 3) * 2 + q;
                                int r = row0 + mwarp * 64 + mt * 16 + (lane >> 2) + h * 8;
                                int p = atomicAdd(&g_cnt[r], 1);
                                if (p < CAP) g_cand[(size_t)r * CAP + p] = (unsigned)c;
                            }
                        }
            }
            #pragma unroll
            for (int i = 0; i < 8; i++) {
                float o = __shfl_xor_sync(0xFFFFFFFFu, rmax[i], 1);
                rmax[i] = fmaxf(rmax[i], o);
                o = __shfl_xor_sync(0xFFFFFFFFu, rmax[i], 2);
                rmax[i] = fmaxf(rmax[i], o);
            }
        }
    } else {
        // ================= FFMA SCREEN (codes FBASE..NCODES) ===============
        const int fwid = blockIdx.y * 2 + (wid - 8);   // 0..17
        const int cbeg = FBASE + fwid * FPW;
        const int cend = min(cbeg + FPW, NCODES);
        const int rg = lane >> 1;         // 0..15  (4 rows each)
        const int cg = lane & 1;          // 0..1   (4 codes each)

        float rmf[8];
        #pragma unroll
        for (int i = 0; i < 8; i++) rmf[i] = __int_as_float(0xff800000);

        for (int cb = cbeg; cb < cend; cb += 8) {
            const int code0 = cb + cg * 4;
            const float* ep[4];
            #pragma unroll
            for (int c = 0; c < 4; c++) {
                int cc = min(code0 + c, NCODES - 1);
                ep[c] = emb + (size_t)cc * D;
            }
            #pragma unroll
            for (int rh = 0; rh < 2; rh++) {
                const int r0 = rh * 64 + rg * 4;
                unsigned long long acc[4][4];
                #pragma unroll
                for (int r = 0; r < 4; r++)
                    #pragma unroll
                    for (int c = 0; c < 4; c++) acc[r][c] = 0ull;

                // e prefetched one k-pair ahead (hides L2/L1 latency)
                unsigned long long ev[4], evn[4];
                #pragma unroll
                for (int c = 0; c < 4; c++)
                    ev[c] = *(const unsigned long long*)(ep[c]);

                #pragma unroll 2
                for (int k2 = 0; k2 < 72; k2++) {
                    if (k2 < 71) {
                        #pragma unroll
                        for (int c = 0; c < 4; c++)
                            evn[c] = *(const unsigned long long*)(ep[c] + 2 * (k2 + 1));
                    }
                    unsigned long long zp[4];
                    #pragma unroll
                    for (int r = 0; r < 4; r++)
                        zp[r] = h2f2(*(const unsigned*)(As + (r0 + r) * ASTRIDE + 2 * k2));
                    #pragma unroll
                    for (int r = 0; r < 4; r++)
                        #pragma unroll
                        for (int c = 0; c < 4; c++)
                            FMA2(acc[r][c], zp[r], ev[c]);
                    #pragma unroll
                    for (int c = 0; c < 4; c++) ev[c] = evn[c];
                }

                // rmax pass
                #pragma unroll
                for (int r = 0; r < 4; r++)
                    #pragma unroll
                    for (int c = 0; c < 4; c++) {
                        float lo, hi; UNPK(lo, hi, acc[r][c]);
                        rmf[rh * 4 + r] = fmaxf(rmf[rh * 4 + r], lo + hi);
                    }
                // pool across the cg pair (same rows)
                #pragma unroll
                for (int r = 0; r < 4; r++) {
                    float o = __shfl_xor_sync(0xFFFFFFFFu, rmf[rh * 4 + r], 1);
                    rmf[rh * 4 + r] = fmaxf(rmf[rh * 4 + r], o);
                }
                // capture pass
                #pragma unroll
                for (int r = 0; r < 4; r++)
                    #pragma unroll
                    for (int c = 0; c < 4; c++) {
                        float lo, hi; UNPK(lo, hi, acc[r][c]);
                        float dot = lo + hi;
                        int code = code0 + c;
                        if (code < cend && dot >= rmf[rh * 4 + r] - CAPW_F) {
                            int rrow = row0 + r0 + r;
                            int p = atomicAdd(&g_cnt[rrow], 1);
                            if (p < CAP) g_cand[(size_t)rrow * CAP + p] = (unsigned)code;
                        }
                    }
            }
        }
    }
}

// ===========================================================================
// Kernel 3: fused exact rescore + gather (bit-identical scoring semantics;
// overflow rows fall back to an exact full scan). grid NROWS, block 64.
// ===========================================================================
__global__ void rescore_gather_kernel(const float* __restrict__ z,
                                      const float* __restrict__ emb,
                                      float* __restrict__ out) {
    const int row = blockIdx.x;
    const int tid = threadIdx.x;
    __shared__ float zs[D];
    __shared__ unsigned long long wkey[2];
    __shared__ float ws[2];

    for (int k = tid; k < D; k += 64) zs[k] = z[(size_t)row * D + k];
    __syncthreads();

    const float zn = g_zn[row];
    const int raw = g_cnt[row];
    const bool ovf = raw > CAP;
    const int cnt = ovf ? NCODES : raw;

    unsigned long long best = 0xFFFFFFFFFFFFFFFFull;
    for (int i = tid; i < cnt; i += 64) {
        unsigned c = ovf ? (unsigned)i : g_cand[(size_t)row * CAP + i];
        const float4* e = (const float4*)(emb + (size_t)c * D);
        float acc = 0.f;
        #pragma unroll
        for (int q = 0; q < 36; q++) {
            float4 ev = e[q];
            acc = __fmaf_rn(zs[q * 4 + 0], ev.x, acc);
            acc = __fmaf_rn(zs[q * 4 + 1], ev.y, acc);
            acc = __fmaf_rn(zs[q * 4 + 2], ev.z, acc);
            acc = __fmaf_rn(zs[q * 4 + 3], ev.w, acc);
        }
        float t = __fadd_rn(zn, g_nrm[c]);
        float s = __fmaf_rn(acc, -2.f, t);
        unsigned long long key = ((unsigned long long)ordered_bits(s) << 32) | c;
        if (key < best) best = key;
    }
    #pragma unroll
    for (int off = 16; off >= 1; off >>= 1) {
        unsigned long long o = __shfl_xor_sync(0xFFFFFFFFu, best, off);
        if (o < best) best = o;
    }
    if ((tid & 31) == 0) wkey[tid >> 5] = best;
    __syncthreads();
    unsigned long long kmin = wkey[0] < wkey[1] ? wkey[0] : wkey[1];
    unsigned idx = (unsigned)(kmin & 0xFFFFFFFFull);
    if (idx >= NCODES) idx = 0;   // defensive (no-op when capture is sound)

    // gather + loss partial
    const float* e = emb + (size_t)idx * D;
    float s = 0.f;
    for (int d = tid; d < D; d += 64) {
        float q = e[d];
        out[(size_t)row * D + d] = q;
        float df = q - zs[d];
        s += df * df;
    }
    #pragma unroll
    for (int off = 16; off >= 1; off >>= 1)
        s += __shfl_xor_sync(0xFFFFFFFFu, s, off);
    if ((tid & 31) == 0) ws[tid >> 5] = s;
    __syncthreads();
    if (tid == 0) {
        g_part[row] = ws[0] + ws[1];
        out[ZQ_ELEMS + row] = (float)idx;
    }
}

// ===========================================================================
// Kernel 4: loss (deterministic reduction)
// ===========================================================================
__global__ void finalize_kernel(float* __restrict__ out, int out_size) {
    __shared__ float sh[256];
    float s = 0.f;
    for (int i = threadIdx.x; i < NROWS; i += 256) s += g_part[i];
    sh[threadIdx.x] = s;
    __syncthreads();
    for (int off = 128; off >= 1; off >>= 1) {
        if (threadIdx.x < off) sh[threadIdx.x] += sh[threadIdx.x + off];
        __syncthreads();
    }
    if (threadIdx.x == 0)
        out[out_size - 1] = sh[0] / (float)(ZQ_ELEMS);
}

// ===========================================================================
extern "C" void kernel_launch(void* const* d_in, const int* in_sizes, int n_in,
                              void* d_out, int out_size) {
    const float* z   = (const float*)d_in[0];
    const float* emb = (const float*)d_in[1];
    float* out = (float*)d_out;

    prep_kernel<<<(NCODES + 255) / 256, 256>>>(z, emb);
    screen_kernel<<<dim3(NROWS / BM, NSPLIT), 320>>>(z, emb);
    rescore_gather_kernel<<<NROWS, 64>>>(z, emb, out);
    finalize_kernel<<<1, 256>>>(out, out_size);
}

// round 16
// speedup vs baseline: 2.7609x; 2.7609x over previous
#include <cuda_runtime.h>
#include <cuda_fp16.h>
#include <cstdint>

// ===========================================================================
// Problem constants
// ===========================================================================
#define D        144
#define NROWS    4096
#define NCODES   50257
#define ZQ_ELEMS (NROWS * D)

#define BM       128                        // rows per CTA
#define BN       128                        // codes per tile iteration
#define TILES    ((NCODES + BN - 1) / BN)   // 393
#define NSPLIT   9
#define TPS      ((TILES + NSPLIT - 1) / NSPLIT) // 44

#define CAP      2048                       // candidate slots per row
#define ESCALE   1024.0f                    // emb pre-scale (fp16 normal range)
#define CAPW     (3e-5f * ESCALE)           // capture window, scaled dot units
#define ASTRIDE  152                        // A smem row stride (fp16 elems)

// ===========================================================================
// Global scratch (device globals only — no cudaMalloc)
// ===========================================================================
__device__ float    g_nrm[NCODES];
__device__ float    g_zn[NROWS];
__device__ int      g_cnt[NROWS];
__device__ unsigned g_cand[(size_t)NROWS * CAP];
__device__ __align__(16) __half g_embh[(size_t)NCODES * D];
__device__ float    g_loss;
__device__ unsigned g_done;

__device__ __forceinline__ unsigned ordered_bits(float s) {
    unsigned b = __float_as_uint(s);
    return b ^ ((unsigned)((int)b >> 31) | 0x80000000u);
}
__device__ __forceinline__ unsigned pack_h2(float lo, float hi) {
    __half2 h = __floats2half2_rn(lo, hi);
    return *(unsigned*)&h;
}
__device__ __forceinline__ uint32_t smem_u32(const void* p) {
    uint32_t a;
    asm("{ .reg .u64 t; cvta.to.shared.u64 t, %1; cvt.u32.u64 %0, t; }"
        : "=r"(a) : "l"(p));
    return a;
}
__device__ __forceinline__ void ldsm4(unsigned a[4], unsigned addr) {
    asm volatile("ldmatrix.sync.aligned.m8n8.x4.shared.b16 {%0,%1,%2,%3}, [%4];"
                 : "=r"(a[0]), "=r"(a[1]), "=r"(a[2]), "=r"(a[3]) : "r"(addr));
}
// fp16-accumulate HMMA: C/D are 2 regs (each .f16x2)
__device__ __forceinline__ void mma16816h(unsigned c[2], const unsigned a[4],
                                          const unsigned b0, const unsigned b1) {
    asm volatile(
        "mma.sync.aligned.m16n8k16.row.col.f16.f16.f16.f16 "
        "{%0,%1}, {%2,%3,%4,%5}, {%6,%7}, {%0,%1};"
        : "+r"(c[0]), "+r"(c[1])
        : "r"(a[0]), "r"(a[1]), "r"(a[2]), "r"(a[3]), "r"(b0), "r"(b1));
}

// ===========================================================================
// Kernel 1: norms, scaled-fp16 emb copy, scratch reset
// (norm arithmetic bit-identical to every passing round)
// ===========================================================================
__global__ void prep_kernel(const float* __restrict__ z,
                            const float* __restrict__ emb) {
    int t = blockIdx.x * 256 + threadIdx.x;
    if (t == 0) { g_loss = 0.f; g_done = 0u; }
    if (t < NROWS) {
        g_cnt[t] = 0;
        const float4* p = (const float4*)(z + (size_t)t * D);
        float s = 0.f;
        #pragma unroll
        for (int i = 0; i < 36; i++) {
            float4 v = p[i];
            s += v.x * v.x + v.y * v.y + v.z * v.z + v.w * v.w;
        }
        g_zn[t] = s;
    }
    if (t < NCODES) {
        const float4* p = (const float4*)(emb + (size_t)t * D);
        uint2* dst = (uint2*)(g_embh + (size_t)t * D);
        float s = 0.f;
        #pragma unroll
        for (int i = 0; i < 36; i++) {
            float4 v = p[i];
            s += v.x * v.x + v.y * v.y + v.z * v.z + v.w * v.w;
            dst[i] = make_uint2(pack_h2(v.x * ESCALE, v.y * ESCALE),
                                pack_h2(v.z * ESCALE, v.w * ESCALE));
        }
        g_nrm[t] = s;
    }
}

// ===========================================================================
// Kernel 2: fp16 mma.sync screening — byte-identical to the R12 champion.
// grid(32, 9), 256 threads (warps 2m x 4n, warp tile 64x32), 2 CTAs/SM
// ===========================================================================
__device__ __forceinline__ void loadB(unsigned b[4][2], int c0, int ks,
                                      int nwarp, int lane) {
    #pragma unroll
    for (int nt = 0; nt < 4; nt++) {
        int code = c0 + nwarp * 32 + nt * 8 + (lane >> 2);
        if (code < NCODES) {
            const __half* p =
                g_embh + (size_t)code * D + ks * 16 + (lane & 3) * 2;
            b[nt][0] = *(const unsigned*)p;
            b[nt][1] = *(const unsigned*)(p + 8);
        } else {
            b[nt][0] = 0u; b[nt][1] = 0u;
        }
    }
}

__global__ void __launch_bounds__(256, 2)
screen_kernel(const float* __restrict__ z) {
    __shared__ __half As[BM * ASTRIDE];

    const int tid  = threadIdx.x;
    const int lane = tid & 31;
    const int wid  = tid >> 5;
    const int mwarp = wid >> 2;       // 0..1
    const int nwarp = wid & 3;        // 0..3
    const int row0 = blockIdx.x * BM;

    // Load z tile -> fp16 smem (row-major, stride 152). 2 threads per row.
    {
        int row = tid >> 1, half = tid & 1;
        const float4* src = (const float4*)(z + (size_t)(row0 + row) * D + half * 72);
        unsigned eo = row * ASTRIDE + half * 72;
        #pragma unroll
        for (int j = 0; j < 18; j++) {
            float4 v = src[j];
            *(uint2*)(As + eo + j * 4) =
                make_uint2(pack_h2(v.x, v.y), pack_h2(v.z, v.w));
        }
    }
    __syncthreads();

    const unsigned asbase = smem_u32(As);
    const int tile0 = blockIdx.y * TPS;
    const int tile1 = min(tile0 + TPS, TILES);

    float rmax[8];
    #pragma unroll
    for (int i = 0; i < 8; i++) rmax[i] = __int_as_float(0xff800000);

    for (int ti = tile0; ti < tile1; ++ti) {
        const int c0 = ti * BN;

        unsigned acc[4][4][2];
        #pragma unroll
        for (int mt = 0; mt < 4; mt++)
            #pragma unroll
            for (int nt = 0; nt < 4; nt++) {
                acc[mt][nt][0] = 0u; acc[mt][nt][1] = 0u;  // half2 zeros
            }

        unsigned b[4][2], bn[4][2];
        loadB(b, c0, 0, nwarp, lane);

        #pragma unroll
        for (int ks = 0; ks < 9; ks++) {
            if (ks < 8) loadB(bn, c0, ks + 1, nwarp, lane);
            unsigned a[4][4];
            #pragma unroll
            for (int mt = 0; mt < 4; mt++) {
                unsigned arow = mwarp * 64 + mt * 16 + (lane & 15);
                unsigned abyte = (arow * ASTRIDE + ks * 16 + (lane >> 4) * 8) * 2;
                ldsm4(a[mt], asbase + abyte);
            }
            #pragma unroll
            for (int mt = 0; mt < 4; mt++)
                #pragma unroll
                for (int nt = 0; nt < 4; nt++)
                    mma16816h(acc[mt][nt], a[mt], b[nt][0], b[nt][1]);
            #pragma unroll
            for (int nt = 0; nt < 4; nt++) {
                b[nt][0] = bn[nt][0]; b[nt][1] = bn[nt][1];
            }
        }

        // Epilogue (R12/R4 order): per-lane running-max update + capture, then pool.
        // f16 C layout: reg h: row = lane>>2 + 8h; cols = (lane&3)*2 + {0,1}.
        #pragma unroll
        for (int mt = 0; mt < 4; mt++) {
            float vf[4][2][2];
            #pragma unroll
            for (int nt = 0; nt < 4; nt++)
                #pragma unroll
                for (int h = 0; h < 2; h++) {
                    __half2 hv = *(__half2*)&acc[mt][nt][h];
                    float2 f = __half22float2(hv);
                    vf[nt][h][0] = f.x;
                    vf[nt][h][1] = f.y;
                    rmax[mt * 2 + h] = fmaxf(rmax[mt * 2 + h], fmaxf(f.x, f.y));
                }
            #pragma unroll
            for (int nt = 0; nt < 4; nt++)
                #pragma unroll
                for (int h = 0; h < 2; h++)
                    #pragma unroll
                    for (int q = 0; q < 2; q++) {
                        float v = vf[nt][h][q];
                        if (v >= rmax[mt * 2 + h] - CAPW) {
                            int c = c0 + nwarp * 32 + nt * 8 + (lane & 3) * 2 + q;
                            if (c < NCODES) {
                                int r = row0 + mwarp * 64 + mt * 16 + (lane >> 2) + h * 8;
                                int p = atomicAdd(&g_cnt[r], 1);
                                if (p < CAP) g_cand[(size_t)r * CAP + p] = (unsigned)c;
                            }
                        }
                    }
        }
        // Pool rmax across the 4 lanes that share each row
        #pragma unroll
        for (int i = 0; i < 8; i++) {
            float o = __shfl_xor_sync(0xFFFFFFFFu, rmax[i], 1);
            rmax[i] = fmaxf(rmax[i], o);
            o = __shfl_xor_sync(0xFFFFFFFFu, rmax[i], 2);
            rmax[i] = fmaxf(rmax[i], o);
        }
    }
}

// ===========================================================================
// Kernel 3: fused exact rescore + gather + loss accumulation.
// Scoring arithmetic bit-identical to every passing round. Overflow rows
// fall back to an exact full scan. Last block writes the loss.
// grid NROWS, block 64.
// ===========================================================================
__global__ void rescore_gather_kernel(const float* __restrict__ z,
                                      const float* __restrict__ emb,
                                      float* __restrict__ out,
                                      int out_size) {
    const int row = blockIdx.x;
    const int tid = threadIdx.x;
    __shared__ float zs[D];
    __shared__ unsigned long long wkey[2];
    __shared__ float ws[2];

    for (int k = tid; k < D; k += 64) zs[k] = z[(size_t)row * D + k];
    __syncthreads();

    const float zn = g_zn[row];
    const int raw = g_cnt[row];
    const bool ovf = raw > CAP;
    const int cnt = ovf ? NCODES : raw;

    unsigned long long best = 0xFFFFFFFFFFFFFFFFull;
    for (int i = tid; i < cnt; i += 64) {
        unsigned c = ovf ? (unsigned)i : g_cand[(size_t)row * CAP + i];
        const float4* e = (const float4*)(emb + (size_t)c * D);
        float acc = 0.f;
        #pragma unroll
        for (int q = 0; q < 36; q++) {
            float4 ev = e[q];
            acc = __fmaf_rn(zs[q * 4 + 0], ev.x, acc);
            acc = __fmaf_rn(zs[q * 4 + 1], ev.y, acc);
            acc = __fmaf_rn(zs[q * 4 + 2], ev.z, acc);
            acc = __fmaf_rn(zs[q * 4 + 3], ev.w, acc);
        }
        float t = __fadd_rn(zn, g_nrm[c]);
        float s = __fmaf_rn(acc, -2.f, t);
        unsigned long long key = ((unsigned long long)ordered_bits(s) << 32) | c;
        if (key < best) best = key;
    }
    #pragma unroll
    for (int off = 16; off >= 1; off >>= 1) {
        unsigned long long o = __shfl_xor_sync(0xFFFFFFFFu, best, off);
        if (o < best) best = o;
    }
    if ((tid & 31) == 0) wkey[tid >> 5] = best;
    __syncthreads();
    unsigned long long kmin = wkey[0] < wkey[1] ? wkey[0] : wkey[1];
    unsigned idx = (unsigned)(kmin & 0xFFFFFFFFull);
    if (idx >= NCODES) idx = 0;   // defensive (no-op when capture is sound)

    // gather + per-row squared-error partial
    const float* e = emb + (size_t)idx * D;
    float s = 0.f;
    for (int d = tid; d < D; d += 64) {
        float q = e[d];
        out[(size_t)row * D + d] = q;
        float df = q - zs[d];
        s += df * df;
    }
    #pragma unroll
    for (int off = 16; off >= 1; off >>= 1)
        s += __shfl_xor_sync(0xFFFFFFFFu, s, off);
    if ((tid & 31) == 0) ws[tid >> 5] = s;
    __syncthreads();

    if (tid == 0) {
        out[ZQ_ELEMS + row] = (float)idx;
        atomicAdd(&g_loss, ws[0] + ws[1]);
        __threadfence();
        unsigned done = atomicAdd(&g_done, 1u);
        if (done == NROWS - 1) {
            float total = atomicAdd(&g_loss, 0.f);   // ordered read
            out[out_size - 1] = total / (float)(ZQ_ELEMS);
        }
    }
}

// ===========================================================================
extern "C" void kernel_launch(void* const* d_in, const int* in_sizes, int n_in,
                              void* d_out, int out_size) {
    const float* z   = (const float*)d_in[0];
    const float* emb = (const float*)d_in[1];
    float* out = (float*)d_out;

    prep_kernel<<<(NCODES + 255) / 256, 256>>>(z, emb);
    screen_kernel<<<dim3(NROWS / BM, NSPLIT), 256>>>(z);
    rescore_gather_kernel<<<NROWS, 64>>>(z, emb, out, out_size);
}